// round 15
// baseline (speedup 1.0000x reference)
#include <cuda_runtime.h>
#include <math.h>

// Problem shape (fixed by reference setup_inputs)
#define BATCH  2
#define DDIM   1024
#define NST    16
#define LEN    2048
#define ROWS   (BATCH * DDIM)     // 2048
#define CHUNKS 32
#define CLEN   (LEN / CHUNKS)     // 64
#define SUBT   32                 // phase1 staging subtile
#define SUBT3  16                 // phase3 pipelined subtile
#define NSUB3  (CLEN / SUBT3)     // 4
#define BPITCH 20                 // B/C smem pitch in floats (80B, 16B-aligned)
#define TPITCH 36                 // phase1 row-tile pitch (144B, 16B-aligned)
#define TP3    20                 // phase3 row-tile pitch (80B, 16B-aligned)
#define LOG2E    1.4426950408889634f
#define RCP_LOG2 0.6931471805599453f

// Scratch (no cudaMalloc allowed)
__device__ float g_spt  [LEN * ROWS];           // softplus(delta), transposed [t][row]
__device__ float g_hloc [ROWS * CHUNKS * NST];  // per-chunk local final state
__device__ float g_sumsp[ROWS * CHUNKS];        // per-chunk sum of softplus
__device__ float g_carry[ROWS * CHUNKS * NST];  // carry-in state per chunk

typedef unsigned long long u64;

union F4P { float4 v; u64 p[2]; };
union U2F { u64 u; float f[2]; };

__device__ __forceinline__ u64 mul2(u64 a, u64 b) {
    u64 d;
    asm("mul.rn.f32x2 %0, %1, %2;" : "=l"(d) : "l"(a), "l"(b));
    return d;
}
__device__ __forceinline__ u64 fma2(u64 a, u64 b, u64 c) {
    u64 d;
    asm("fma.rn.f32x2 %0, %1, %2, %3;" : "=l"(d) : "l"(a), "l"(b), "l"(c));
    return d;
}
__device__ __forceinline__ u64 add2(u64 a, u64 b) {
    u64 d;
    asm("add.rn.f32x2 %0, %1, %2;" : "=l"(d) : "l"(a), "l"(b));
    return d;
}
__device__ __forceinline__ u64 splat2(float x) {
    U2F r; r.f[0] = x; r.f[1] = x; return r.u;
}

__device__ __forceinline__ float ex2f(float x) {
    float y;
    asm("ex2.approx.ftz.f32 %0, %1;" : "=f"(y) : "f"(x));
    return y;
}
__device__ __forceinline__ float lg2f(float x) {
    float y;
    asm("lg2.approx.ftz.f32 %0, %1;" : "=f"(y) : "f"(x));
    return y;
}
__device__ __forceinline__ float softplus_f(float x) {
    if (x > 20.0f) return x;
    return lg2f(1.0f + ex2f(x * LOG2E)) * RCP_LOG2;
}
__device__ __forceinline__ float silu_f(float x) {
    float e = ex2f(-x * LOG2E);
    return __fdividef(x, 1.0f + e);
}

// exp2 of both halves via MUFU (XU pipe) — proven fastest variant (round 8).
__device__ __forceinline__ u64 ex2_pair(u64 x2) {
    U2F in; in.u = x2;
    U2F out;
    out.f[0] = ex2f(in.f[0]);
    out.f[1] = ex2f(in.f[1]);
    return out.u;
}

// ------------------------------------------------------------------ phase 1
// (R8 verbatim — measured at its MUFU roofline, do not touch)
__global__ void __launch_bounds__(128) phase1_kernel(const float* __restrict__ u,
                                                     const float* __restrict__ delta,
                                                     const float* __restrict__ A,
                                                     const float* __restrict__ B) {
    __shared__ __align__(16) float Bsm[CLEN][BPITCH];
    __shared__ __align__(16) float Dt[128][TPITCH];
    __shared__ __align__(16) float Ut[128][TPITCH];

    const int tid     = threadIdx.x;
    const int rowbase = blockIdx.x * 128;
    const int row     = rowbase + tid;
    const int chunk   = blockIdx.y;
    const int b       = row >> 10;         // DDIM = 1024
    const int d       = row & (DDIM - 1);
    const int t0      = chunk * CLEN;

    const float* __restrict__ Bb = B + (size_t)b * NST * LEN + t0;
    #pragma unroll
    for (int i = tid; i < NST * (CLEN / 4); i += 128) {
        const int nn = i >> 4;
        const int t4 = (i & 15) << 2;
        float4 v = *reinterpret_cast<const float4*>(Bb + nn * LEN + t4);
        Bsm[t4 + 0][nn] = v.x; Bsm[t4 + 1][nn] = v.y;
        Bsm[t4 + 2][nn] = v.z; Bsm[t4 + 3][nn] = v.w;
    }

    u64 A2p[8];
    {
        const u64 l2 = splat2(LOG2E);
        const float4* Ap = reinterpret_cast<const float4*>(A + d * NST);
        #pragma unroll
        for (int q = 0; q < 4; q++) {
            F4P a; a.v = Ap[q];
            A2p[q*2+0] = mul2(a.p[0], l2);
            A2p[q*2+1] = mul2(a.p[1], l2);
        }
    }

    u64 h2[8];
    #pragma unroll
    for (int p = 0; p < 8; p++) h2[p] = 0ull;
    float ssum = 0.0f;

    #pragma unroll 1
    for (int sub = 0; sub < CLEN / SUBT; sub++) {
        const int tb = t0 + sub * SUBT;
        __syncthreads();
        #pragma unroll
        for (int s = 0; s < 8; s++) {
            const int f = s * 128 + tid;
            const int r = f >> 3;
            const int c = (f & 7) << 2;
            const size_t gofs = (size_t)(rowbase + r) * LEN + tb + c;
            *reinterpret_cast<float4*>(&Dt[r][c]) =
                *reinterpret_cast<const float4*>(delta + gofs);
            *reinterpret_cast<float4*>(&Ut[r][c]) =
                *reinterpret_cast<const float4*>(u + gofs);
        }
        __syncthreads();

        float* __restrict__ sptp = g_spt + (size_t)tb * ROWS + row;

        #pragma unroll 1
        for (int tq = 0; tq < SUBT; tq += 4) {
            float4 d4 = *reinterpret_cast<const float4*>(&Dt[tid][tq]);
            float4 u4 = *reinterpret_cast<const float4*>(&Ut[tid][tq]);
            float sp[4] = {softplus_f(d4.x), softplus_f(d4.y),
                           softplus_f(d4.z), softplus_f(d4.w)};
            float uu[4] = {u4.x, u4.y, u4.z, u4.w};

            #pragma unroll
            for (int k = 0; k < 4; k++) {
                const int tt = sub * SUBT + tq + k;
                sptp[(size_t)(tq + k) * ROWS] = sp[k];
                ssum += sp[k];
                const u64 sp2  = splat2(sp[k]);
                const u64 dbu2 = splat2(sp[k] * uu[k]);

                const float4* Bt = reinterpret_cast<const float4*>(&Bsm[tt][0]);
                F4P b0, b1, b2, b3;
                b0.v = Bt[0]; b1.v = Bt[1]; b2.v = Bt[2]; b3.v = Bt[3];
                const u64 B2[8] = {b0.p[0], b0.p[1], b1.p[0], b1.p[1],
                                   b2.p[0], b2.p[1], b3.p[0], b3.p[1]};
                #pragma unroll
                for (int p = 0; p < 8; p++) {
                    const u64 a2 = ex2_pair(mul2(sp2, A2p[p]));
                    h2[p] = fma2(a2, h2[p], mul2(dbu2, B2[p]));
                }
            }
        }
    }

    float* __restrict__ hp = g_hloc + ((size_t)row * CHUNKS + chunk) * NST;
    #pragma unroll
    for (int q = 0; q < 4; q++) {
        F4P o; o.p[0] = h2[q*2+0]; o.p[1] = h2[q*2+1];
        *reinterpret_cast<float4*>(hp + q * 4) = o.v;
    }
    g_sumsp[row * CHUNKS + chunk] = ssum;
}

// ------------------------------------------------------------------ phase 2
__global__ void __launch_bounds__(256) phase2_kernel(const float* __restrict__ A) {
    const int idx = blockIdx.x * blockDim.x + threadIdx.x;
    const int row = idx >> 4;
    const int n   = idx & (NST - 1);
    const int d   = row & (DDIM - 1);
    const float A2 = A[d * NST + n] * LOG2E;

    float H = 0.0f;
    #pragma unroll
    for (int c = 0; c < CHUNKS; c++) {
        g_carry[((size_t)row * CHUNKS + c) * NST + n] = H;
        float P = ex2f(A2 * g_sumsp[row * CHUNKS + c]);
        H = fmaf(P, H, g_hloc[((size_t)row * CHUNKS + c) * NST + n]);
    }
}

// ------------------------------------------------------------------ phase 3
// Software-pipelined: u/z for subtile k+1 prefetched into registers during
// subtile k's compute; tile refill merged with the y sweep (read y, overwrite
// with u, STG y — one pass, 2 barriers/subtile, no exposed LDG latency).
__global__ void __launch_bounds__(128, 4)
phase3_kernel(const float* __restrict__ u,
              const float* __restrict__ A,
              const float* __restrict__ B,
              const float* __restrict__ C,
              const float* __restrict__ Dv,
              const float* __restrict__ z,
              float* __restrict__ y) {
    __shared__ __align__(16) float Bsm[CLEN][BPITCH];
    __shared__ __align__(16) float Csm[CLEN][BPITCH];
    __shared__ __align__(16) float Ut[128][TP3];   // u in, y out (reused)
    __shared__ __align__(16) float Zt[128][TP3];

    const int tid     = threadIdx.x;
    const int rowbase = blockIdx.x * 128;
    const int row     = rowbase + tid;
    const int chunk   = blockIdx.y;
    const int b       = row >> 10;
    const int d       = row & (DDIM - 1);
    const int t0      = chunk * CLEN;

    // Slot mapping for staging/sweep: f = s*128+tid -> (r, c)
    // Prefetch subtile 0 into registers (overlaps B/C staging below).
    float4 uR[4], zR[4];
    #pragma unroll
    for (int s = 0; s < 4; s++) {
        const int f = s * 128 + tid;
        const int r = f >> 2;
        const int c = (f & 3) << 2;
        const size_t gofs = (size_t)(rowbase + r) * LEN + t0 + c;
        uR[s] = *reinterpret_cast<const float4*>(u + gofs);
        zR[s] = *reinterpret_cast<const float4*>(z + gofs);
    }

    const float* __restrict__ Bb = B + (size_t)b * NST * LEN + t0;
    const float* __restrict__ Cb = C + (size_t)b * NST * LEN + t0;
    #pragma unroll
    for (int i = tid; i < NST * (CLEN / 4); i += 128) {
        const int nn = i >> 4;
        const int t4 = (i & 15) << 2;
        float4 v = *reinterpret_cast<const float4*>(Bb + nn * LEN + t4);
        Bsm[t4 + 0][nn] = v.x; Bsm[t4 + 1][nn] = v.y;
        Bsm[t4 + 2][nn] = v.z; Bsm[t4 + 3][nn] = v.w;
        float4 w = *reinterpret_cast<const float4*>(Cb + nn * LEN + t4);
        Csm[t4 + 0][nn] = w.x; Csm[t4 + 1][nn] = w.y;
        Csm[t4 + 2][nn] = w.z; Csm[t4 + 3][nn] = w.w;
    }

    u64 A2p[8];
    {
        const u64 l2 = splat2(LOG2E);
        const float4* Ap = reinterpret_cast<const float4*>(A + d * NST);
        #pragma unroll
        for (int q = 0; q < 4; q++) {
            F4P a; a.v = Ap[q];
            A2p[q*2+0] = mul2(a.p[0], l2);
            A2p[q*2+1] = mul2(a.p[1], l2);
        }
    }
    const float Dd = Dv[d];

    u64 h2[8];
    {
        const float4* cp = reinterpret_cast<const float4*>(
            g_carry + ((size_t)row * CHUNKS + chunk) * NST);
        #pragma unroll
        for (int q = 0; q < 4; q++) {
            F4P c4; c4.v = cp[q];
            h2[q*2+0] = c4.p[0];
            h2[q*2+1] = c4.p[1];
        }
    }

    #pragma unroll 1
    for (int sub = 0; sub < NSUB3; sub++) {
        const int tb = t0 + sub * SUBT3;

        __syncthreads();   // prev compute done (y resident in Ut); B/C staged (sub 0)

        // Merged sweep(y of sub-1) + refill(u,z of sub). Each (r,c) slot is
        // owned by exactly one thread here; y-read precedes u-overwrite at the
        // same address in the same thread, ordered by the barrier above.
        #pragma unroll
        for (int s = 0; s < 4; s++) {
            const int f = s * 128 + tid;
            const int r = f >> 2;
            const int c = (f & 3) << 2;
            float4 yv;
            if (sub > 0) yv = *reinterpret_cast<const float4*>(&Ut[r][c]);
            *reinterpret_cast<float4*>(&Ut[r][c]) = uR[s];
            *reinterpret_cast<float4*>(&Zt[r][c]) = zR[s];
            if (sub > 0) {
                *reinterpret_cast<float4*>(
                    y + (size_t)(rowbase + r) * LEN + (tb - SUBT3) + c) = yv;
            }
        }

        // Prefetch next subtile (latency hidden under this subtile's compute).
        if (sub + 1 < NSUB3) {
            #pragma unroll
            for (int s = 0; s < 4; s++) {
                const int f = s * 128 + tid;
                const int r = f >> 2;
                const int c = (f & 3) << 2;
                const size_t gofs = (size_t)(rowbase + r) * LEN + tb + SUBT3 + c;
                uR[s] = *reinterpret_cast<const float4*>(u + gofs);
                zR[s] = *reinterpret_cast<const float4*>(z + gofs);
            }
        }
        __syncthreads();   // tiles ready

        const float* __restrict__ sptp = g_spt + (size_t)tb * ROWS + row;

        #pragma unroll 1
        for (int tq = 0; tq < SUBT3; tq += 4) {
            float4 u4 = *reinterpret_cast<const float4*>(&Ut[tid][tq]);
            float4 z4 = *reinterpret_cast<const float4*>(&Zt[tid][tq]);
            float uu[4] = {u4.x, u4.y, u4.z, u4.w};
            float zz[4] = {z4.x, z4.y, z4.z, z4.w};
            float r4[4];

            #pragma unroll
            for (int k = 0; k < 4; k++) {
                const int tt    = sub * SUBT3 + tq + k;
                const float spv = sptp[(size_t)(tq + k) * ROWS];
                const float uv  = uu[k];
                const u64 sp2   = splat2(spv);
                const u64 dbu2  = splat2(spv * uv);

                const float4* Bt = reinterpret_cast<const float4*>(&Bsm[tt][0]);
                const float4* Ct = reinterpret_cast<const float4*>(&Csm[tt][0]);
                F4P b0, b1, b2, b3, c0, c1, c2, c3;
                b0.v = Bt[0]; b1.v = Bt[1]; b2.v = Bt[2]; b3.v = Bt[3];
                c0.v = Ct[0]; c1.v = Ct[1]; c2.v = Ct[2]; c3.v = Ct[3];
                const u64 B2[8] = {b0.p[0], b0.p[1], b1.p[0], b1.p[1],
                                   b2.p[0], b2.p[1], b3.p[0], b3.p[1]};
                const u64 C2[8] = {c0.p[0], c0.p[1], c1.p[0], c1.p[1],
                                   c2.p[0], c2.p[1], c3.p[0], c3.p[1]};

                u64 accA = 0ull, accB = 0ull;
                #pragma unroll
                for (int p = 0; p < 8; p += 2) {
                    const u64 a2_0 = ex2_pair(mul2(sp2, A2p[p]));
                    h2[p] = fma2(a2_0, h2[p], mul2(dbu2, B2[p]));
                    accA = fma2(C2[p], h2[p], accA);
                    const u64 a2_1 = ex2_pair(mul2(sp2, A2p[p+1]));
                    h2[p+1] = fma2(a2_1, h2[p+1], mul2(dbu2, B2[p+1]));
                    accB = fma2(C2[p+1], h2[p+1], accB);
                }
                U2F acc; acc.u = add2(accA, accB);
                const float s = (acc.f[0] + acc.f[1]) + uv * Dd;
                r4[k] = s * silu_f(zz[k]);
            }

            // y into own row's consumed u slots
            *reinterpret_cast<float4*>(&Ut[tid][tq]) =
                make_float4(r4[0], r4[1], r4[2], r4[3]);
        }
    }

    // Final sweep: y of last subtile
    __syncthreads();
    #pragma unroll
    for (int s = 0; s < 4; s++) {
        const int f = s * 128 + tid;
        const int r = f >> 2;
        const int c = (f & 3) << 2;
        *reinterpret_cast<float4*>(
            y + (size_t)(rowbase + r) * LEN + t0 + (NSUB3 - 1) * SUBT3 + c) =
            *reinterpret_cast<const float4*>(&Ut[r][c]);
    }
}

extern "C" void kernel_launch(void* const* d_in, const int* in_sizes, int n_in,
                              void* d_out, int out_size) {
    // metadata order: u, delta, A, B, C, D, z, delta_softplus
    const float* u     = (const float*)d_in[0];
    const float* delta = (const float*)d_in[1];
    const float* A     = (const float*)d_in[2];
    const float* B     = (const float*)d_in[3];
    const float* C     = (const float*)d_in[4];
    const float* D     = (const float*)d_in[5];
    const float* z     = (const float*)d_in[6];
    float* y = (float*)d_out;

    dim3 grid1(ROWS / 128, CHUNKS);
    phase1_kernel<<<grid1, 128>>>(u, delta, A, B);
    phase2_kernel<<<(ROWS * NST) / 256, 256>>>(A);
    phase3_kernel<<<grid1, 128>>>(u, A, B, C, D, z, y);
}

// round 16
// speedup vs baseline: 1.0167x; 1.0167x over previous
#include <cuda_runtime.h>
#include <math.h>

// Problem shape (fixed by reference setup_inputs)
#define BATCH  2
#define DDIM   1024
#define NST    16
#define LEN    2048
#define ROWS   (BATCH * DDIM)     // 2048
#define CHUNKS 32
#define CLEN   (LEN / CHUNKS)     // 64
#define SUBT   32                 // staging subtile (timesteps) = 128B rows
#define BPITCH 20                 // B/C smem pitch in floats (80B, 16B-aligned)
#define TPITCH 36                 // row-tile pitch in floats (144B, 16B-aligned)
#define LOG2E    1.4426950408889634f
#define RCP_LOG2 0.6931471805599453f

// Scratch (no cudaMalloc allowed)
__device__ float g_spt  [LEN * ROWS];           // softplus(delta), transposed [t][row]
__device__ float g_hloc [ROWS * CHUNKS * NST];  // per-chunk local final state
__device__ float g_sumsp[ROWS * CHUNKS];        // per-chunk sum of softplus
__device__ float g_carry[ROWS * CHUNKS * NST];  // carry-in state per chunk
__device__ float g_probe[1];                    // dummy sink

typedef unsigned long long u64;

union F4P { float4 v; u64 p[2]; };
union U2F { u64 u; float f[2]; };

__device__ __forceinline__ u64 mul2(u64 a, u64 b) {
    u64 d;
    asm("mul.rn.f32x2 %0, %1, %2;" : "=l"(d) : "l"(a), "l"(b));
    return d;
}
__device__ __forceinline__ u64 fma2(u64 a, u64 b, u64 c) {
    u64 d;
    asm("fma.rn.f32x2 %0, %1, %2, %3;" : "=l"(d) : "l"(a), "l"(b), "l"(c));
    return d;
}
__device__ __forceinline__ u64 add2(u64 a, u64 b) {
    u64 d;
    asm("add.rn.f32x2 %0, %1, %2;" : "=l"(d) : "l"(a), "l"(b));
    return d;
}
__device__ __forceinline__ u64 splat2(float x) {
    U2F r; r.f[0] = x; r.f[1] = x; return r.u;
}

__device__ __forceinline__ float ex2f(float x) {
    float y;
    asm("ex2.approx.ftz.f32 %0, %1;" : "=f"(y) : "f"(x));
    return y;
}
__device__ __forceinline__ float lg2f(float x) {
    float y;
    asm("lg2.approx.ftz.f32 %0, %1;" : "=f"(y) : "f"(x));
    return y;
}
__device__ __forceinline__ float softplus_f(float x) {
    if (x > 20.0f) return x;
    return lg2f(1.0f + ex2f(x * LOG2E)) * RCP_LOG2;
}
__device__ __forceinline__ float silu_f(float x) {
    float e = ex2f(-x * LOG2E);
    return __fdividef(x, 1.0f + e);
}

// exp2 of both halves via MUFU (XU pipe) — proven fastest variant (round 8).
__device__ __forceinline__ u64 ex2_pair(u64 x2) {
    U2F in; in.u = x2;
    U2F out;
    out.f[0] = ex2f(in.f[0]);
    out.f[1] = ex2f(in.f[1]);
    return out.u;
}

// ------------------------------------------------------------------ probe
// Launch-slot shim: shifts the per-cycle kernel count to 4 so ncu's fixed
// capture slot lands on phase3 (as it did in the 4-kernel round R3).
__global__ void probe_kernel() {
    g_probe[0] = 1.0f;
}

// ------------------------------------------------------------------ phase 1
// (R8 verbatim — measured at its MUFU roofline, do not touch)
__global__ void __launch_bounds__(128) phase1_kernel(const float* __restrict__ u,
                                                     const float* __restrict__ delta,
                                                     const float* __restrict__ A,
                                                     const float* __restrict__ B) {
    __shared__ __align__(16) float Bsm[CLEN][BPITCH];
    __shared__ __align__(16) float Dt[128][TPITCH];
    __shared__ __align__(16) float Ut[128][TPITCH];

    const int tid     = threadIdx.x;
    const int rowbase = blockIdx.x * 128;
    const int row     = rowbase + tid;
    const int chunk   = blockIdx.y;
    const int b       = row >> 10;         // DDIM = 1024
    const int d       = row & (DDIM - 1);
    const int t0      = chunk * CLEN;

    const float* __restrict__ Bb = B + (size_t)b * NST * LEN + t0;
    #pragma unroll
    for (int i = tid; i < NST * (CLEN / 4); i += 128) {
        const int nn = i >> 4;
        const int t4 = (i & 15) << 2;
        float4 v = *reinterpret_cast<const float4*>(Bb + nn * LEN + t4);
        Bsm[t4 + 0][nn] = v.x; Bsm[t4 + 1][nn] = v.y;
        Bsm[t4 + 2][nn] = v.z; Bsm[t4 + 3][nn] = v.w;
    }

    u64 A2p[8];
    {
        const u64 l2 = splat2(LOG2E);
        const float4* Ap = reinterpret_cast<const float4*>(A + d * NST);
        #pragma unroll
        for (int q = 0; q < 4; q++) {
            F4P a; a.v = Ap[q];
            A2p[q*2+0] = mul2(a.p[0], l2);
            A2p[q*2+1] = mul2(a.p[1], l2);
        }
    }

    u64 h2[8];
    #pragma unroll
    for (int p = 0; p < 8; p++) h2[p] = 0ull;
    float ssum = 0.0f;

    #pragma unroll 1
    for (int sub = 0; sub < CLEN / SUBT; sub++) {
        const int tb = t0 + sub * SUBT;
        __syncthreads();
        #pragma unroll
        for (int s = 0; s < 8; s++) {
            const int f = s * 128 + tid;
            const int r = f >> 3;
            const int c = (f & 7) << 2;
            const size_t gofs = (size_t)(rowbase + r) * LEN + tb + c;
            *reinterpret_cast<float4*>(&Dt[r][c]) =
                *reinterpret_cast<const float4*>(delta + gofs);
            *reinterpret_cast<float4*>(&Ut[r][c]) =
                *reinterpret_cast<const float4*>(u + gofs);
        }
        __syncthreads();

        float* __restrict__ sptp = g_spt + (size_t)tb * ROWS + row;

        #pragma unroll 1
        for (int tq = 0; tq < SUBT; tq += 4) {
            float4 d4 = *reinterpret_cast<const float4*>(&Dt[tid][tq]);
            float4 u4 = *reinterpret_cast<const float4*>(&Ut[tid][tq]);
            float sp[4] = {softplus_f(d4.x), softplus_f(d4.y),
                           softplus_f(d4.z), softplus_f(d4.w)};
            float uu[4] = {u4.x, u4.y, u4.z, u4.w};

            #pragma unroll
            for (int k = 0; k < 4; k++) {
                const int tt = sub * SUBT + tq + k;
                sptp[(size_t)(tq + k) * ROWS] = sp[k];
                ssum += sp[k];
                const u64 sp2  = splat2(sp[k]);
                const u64 dbu2 = splat2(sp[k] * uu[k]);

                const float4* Bt = reinterpret_cast<const float4*>(&Bsm[tt][0]);
                F4P b0, b1, b2, b3;
                b0.v = Bt[0]; b1.v = Bt[1]; b2.v = Bt[2]; b3.v = Bt[3];
                const u64 B2[8] = {b0.p[0], b0.p[1], b1.p[0], b1.p[1],
                                   b2.p[0], b2.p[1], b3.p[0], b3.p[1]};
                #pragma unroll
                for (int p = 0; p < 8; p++) {
                    const u64 a2 = ex2_pair(mul2(sp2, A2p[p]));
                    h2[p] = fma2(a2, h2[p], mul2(dbu2, B2[p]));
                }
            }
        }
    }

    float* __restrict__ hp = g_hloc + ((size_t)row * CHUNKS + chunk) * NST;
    #pragma unroll
    for (int q = 0; q < 4; q++) {
        F4P o; o.p[0] = h2[q*2+0]; o.p[1] = h2[q*2+1];
        *reinterpret_cast<float4*>(hp + q * 4) = o.v;
    }
    g_sumsp[row * CHUNKS + chunk] = ssum;
}

// ------------------------------------------------------------------ phase 2
__global__ void __launch_bounds__(256) phase2_kernel(const float* __restrict__ A) {
    const int idx = blockIdx.x * blockDim.x + threadIdx.x;
    const int row = idx >> 4;
    const int n   = idx & (NST - 1);
    const int d   = row & (DDIM - 1);
    const float A2 = A[d * NST + n] * LOG2E;

    float H = 0.0f;
    #pragma unroll
    for (int c = 0; c < CHUNKS; c++) {
        g_carry[((size_t)row * CHUNKS + c) * NST + n] = H;
        float P = ex2f(A2 * g_sumsp[row * CHUNKS + c]);
        H = fmaf(P, H, g_hloc[((size_t)row * CHUNKS + c) * NST + n]);
    }
}

// ------------------------------------------------------------------ phase 3
// R8 structure, with the C-accumulation split into 4 chains (halves the
// per-t serial fma2 depth on the y path; +2 add2 off-path).
__global__ void __launch_bounds__(128) phase3_kernel(const float* __restrict__ u,
                                                     const float* __restrict__ A,
                                                     const float* __restrict__ B,
                                                     const float* __restrict__ C,
                                                     const float* __restrict__ Dv,
                                                     const float* __restrict__ z,
                                                     float* __restrict__ y) {
    __shared__ __align__(16) float Bsm[CLEN][BPITCH];
    __shared__ __align__(16) float Csm[CLEN][BPITCH];
    __shared__ __align__(16) float Ut[128][TPITCH];   // holds u, then reused for y
    __shared__ __align__(16) float Zt[128][TPITCH];

    const int tid     = threadIdx.x;
    const int rowbase = blockIdx.x * 128;
    const int row     = rowbase + tid;
    const int chunk   = blockIdx.y;
    const int b       = row >> 10;
    const int d       = row & (DDIM - 1);
    const int t0      = chunk * CLEN;

    const float* __restrict__ Bb = B + (size_t)b * NST * LEN + t0;
    const float* __restrict__ Cb = C + (size_t)b * NST * LEN + t0;
    #pragma unroll
    for (int i = tid; i < NST * (CLEN / 4); i += 128) {
        const int nn = i >> 4;
        const int t4 = (i & 15) << 2;
        float4 v = *reinterpret_cast<const float4*>(Bb + nn * LEN + t4);
        Bsm[t4 + 0][nn] = v.x; Bsm[t4 + 1][nn] = v.y;
        Bsm[t4 + 2][nn] = v.z; Bsm[t4 + 3][nn] = v.w;
        float4 w = *reinterpret_cast<const float4*>(Cb + nn * LEN + t4);
        Csm[t4 + 0][nn] = w.x; Csm[t4 + 1][nn] = w.y;
        Csm[t4 + 2][nn] = w.z; Csm[t4 + 3][nn] = w.w;
    }

    u64 A2p[8];
    {
        const u64 l2 = splat2(LOG2E);
        const float4* Ap = reinterpret_cast<const float4*>(A + d * NST);
        #pragma unroll
        for (int q = 0; q < 4; q++) {
            F4P a; a.v = Ap[q];
            A2p[q*2+0] = mul2(a.p[0], l2);
            A2p[q*2+1] = mul2(a.p[1], l2);
        }
    }
    const float Dd = Dv[d];

    u64 h2[8];
    {
        const float4* cp = reinterpret_cast<const float4*>(
            g_carry + ((size_t)row * CHUNKS + chunk) * NST);
        #pragma unroll
        for (int q = 0; q < 4; q++) {
            F4P c4; c4.v = cp[q];
            h2[q*2+0] = c4.p[0];
            h2[q*2+1] = c4.p[1];
        }
    }

    #pragma unroll 1
    for (int sub = 0; sub < CLEN / SUBT; sub++) {
        const int tb = t0 + sub * SUBT;
        __syncthreads();   // previous writeout complete / B,C staged
        #pragma unroll
        for (int s = 0; s < 8; s++) {
            const int f = s * 128 + tid;
            const int r = f >> 3;
            const int c = (f & 7) << 2;
            const size_t gofs = (size_t)(rowbase + r) * LEN + tb + c;
            *reinterpret_cast<float4*>(&Ut[r][c]) =
                *reinterpret_cast<const float4*>(u + gofs);
            *reinterpret_cast<float4*>(&Zt[r][c]) =
                *reinterpret_cast<const float4*>(z + gofs);
        }
        __syncthreads();

        const float* __restrict__ sptp = g_spt + (size_t)tb * ROWS + row;

        #pragma unroll 1
        for (int tq = 0; tq < SUBT; tq += 4) {
            float4 u4 = *reinterpret_cast<const float4*>(&Ut[tid][tq]);
            float4 z4 = *reinterpret_cast<const float4*>(&Zt[tid][tq]);
            float uu[4] = {u4.x, u4.y, u4.z, u4.w};
            float zz[4] = {z4.x, z4.y, z4.z, z4.w};
            float r4[4];

            #pragma unroll
            for (int k = 0; k < 4; k++) {
                const int tt    = sub * SUBT + tq + k;
                const float spv = sptp[(size_t)(tq + k) * ROWS];
                const float uv  = uu[k];
                const u64 sp2   = splat2(spv);
                const u64 dbu2  = splat2(spv * uv);

                const float4* Bt = reinterpret_cast<const float4*>(&Bsm[tt][0]);
                const float4* Ct = reinterpret_cast<const float4*>(&Csm[tt][0]);
                F4P b0, b1, b2, b3, c0, c1, c2, c3;
                b0.v = Bt[0]; b1.v = Bt[1]; b2.v = Bt[2]; b3.v = Bt[3];
                c0.v = Ct[0]; c1.v = Ct[1]; c2.v = Ct[2]; c3.v = Ct[3];
                const u64 B2[8] = {b0.p[0], b0.p[1], b1.p[0], b1.p[1],
                                   b2.p[0], b2.p[1], b3.p[0], b3.p[1]};
                const u64 C2[8] = {c0.p[0], c0.p[1], c1.p[0], c1.p[1],
                                   c2.p[0], c2.p[1], c3.p[0], c3.p[1]};

                // 4 independent accumulation chains (depth 2 each)
                u64 acc4[4] = {0ull, 0ull, 0ull, 0ull};
                #pragma unroll
                for (int p = 0; p < 8; p++) {
                    const u64 a2 = ex2_pair(mul2(sp2, A2p[p]));
                    h2[p] = fma2(a2, h2[p], mul2(dbu2, B2[p]));
                    acc4[p & 3] = fma2(C2[p], h2[p], acc4[p & 3]);
                }
                U2F acc;
                acc.u = add2(add2(acc4[0], acc4[1]), add2(acc4[2], acc4[3]));
                const float s = (acc.f[0] + acc.f[1]) + uv * Dd;
                r4[k] = s * silu_f(zz[k]);
            }

            // Reuse the u tile as the y tile (u[tq..tq+3] already consumed)
            *reinterpret_cast<float4*>(&Ut[tid][tq]) =
                make_float4(r4[0], r4[1], r4[2], r4[3]);
        }

        __syncthreads();   // y tile complete
        #pragma unroll
        for (int s = 0; s < 8; s++) {
            const int f = s * 128 + tid;
            const int r = f >> 3;
            const int c = (f & 7) << 2;
            *reinterpret_cast<float4*>(y + (size_t)(rowbase + r) * LEN + tb + c) =
                *reinterpret_cast<const float4*>(&Ut[r][c]);
        }
    }
}

extern "C" void kernel_launch(void* const* d_in, const int* in_sizes, int n_in,
                              void* d_out, int out_size) {
    // metadata order: u, delta, A, B, C, D, z, delta_softplus
    const float* u     = (const float*)d_in[0];
    const float* delta = (const float*)d_in[1];
    const float* A     = (const float*)d_in[2];
    const float* B     = (const float*)d_in[3];
    const float* C     = (const float*)d_in[4];
    const float* D     = (const float*)d_in[5];
    const float* z     = (const float*)d_in[6];
    float* y = (float*)d_out;

    dim3 grid1(ROWS / 128, CHUNKS);
    probe_kernel<<<1, 1>>>();                              // shifts ncu capture slot to phase3
    phase1_kernel<<<grid1, 128>>>(u, delta, A, B);
    phase2_kernel<<<(ROWS * NST) / 256, 256>>>(A);
    phase3_kernel<<<grid1, 128>>>(u, A, B, C, D, z, y);
}